// round 4
// baseline (speedup 1.0000x reference)
#include <cuda_runtime.h>

// gltrivmlp: out[b,g,0:16]=con, out[...,16:32]=clip(con*s),
// out[...,32:48]=clip^2, out[...,48:64]=clip^3, s=rowsum(mat[b,g,:])/16.
// (10-iter reference loop is a 16-lane shift register; fixed point after 3
// iterations; initial val[16:64] is dead.)
//
// R4: split. Kernel A = pure 128MB read stream (mat row-sums -> 4B/row scale
// scratch, L2-resident). Kernel B = tiny epilogue (con read + clip + 8MB out
// write). Quarantines store/partial-line traffic out of the dominant read
// stream to push DRAM read saturation.

#define GS     1024
#define PARAM  64
#define NSM    148
#define ABLKS  (NSM * 8)
#define MAXROWS 65536

__device__ float g_scale[MAXROWS];   // 256 KB scratch (rows actual = 32768)

// ---------------- Kernel A: row sums (pure read stream) ----------------
__global__ __launch_bounds__(256, 8)
void rowsum_kernel(const float* __restrict__ mat, int rows)
{
    const int lane = threadIdx.x & 31;
    const int gw   = blockIdx.x * 8 + (threadIdx.x >> 5);
    const int totw = ABLKS * 8;      // 9472

    for (int row = gw; row < rows; row += totw) {
        const float4* m = reinterpret_cast<const float4*>(mat + (size_t)row * GS);
        float4 v0 = __ldcs(&m[lane +   0]);
        float4 v1 = __ldcs(&m[lane +  32]);
        float4 v2 = __ldcs(&m[lane +  64]);
        float4 v3 = __ldcs(&m[lane +  96]);
        float4 v4 = __ldcs(&m[lane + 128]);
        float4 v5 = __ldcs(&m[lane + 160]);
        float4 v6 = __ldcs(&m[lane + 192]);
        float4 v7 = __ldcs(&m[lane + 224]);
        float a0 = ((v0.x + v0.y) + (v0.z + v0.w)) + ((v1.x + v1.y) + (v1.z + v1.w));
        float a1 = ((v2.x + v2.y) + (v2.z + v2.w)) + ((v3.x + v3.y) + (v3.z + v3.w));
        float a2 = ((v4.x + v4.y) + (v4.z + v4.w)) + ((v5.x + v5.y) + (v5.z + v5.w));
        float a3 = ((v6.x + v6.y) + (v6.z + v6.w)) + ((v7.x + v7.y) + (v7.z + v7.w));

        float s = (a0 + a1) + (a2 + a3);
        #pragma unroll
        for (int o = 16; o > 0; o >>= 1)
            s += __shfl_xor_sync(0xFFFFFFFFu, s, o);

        if (lane == 0)
            g_scale[row] = s * (1.0f / 16.0f);
    }
}

// ---------------- Kernel B: epilogue (con -> clipped powers -> out) -----
__global__ __launch_bounds__(256)
void epilogue_kernel(const float* __restrict__ val,
                     float* __restrict__ out, int rows)
{
    const int lane = threadIdx.x & 31;
    const int row  = blockIdx.x * 8 + (threadIdx.x >> 5);
    if (row >= rows) return;

    const float scale = g_scale[row];

    // lane -> output elements {2*lane, 2*lane+1}; both in group g
    const int e0 = lane << 1;
    const int g  = e0 >> 4;          // clip applications: 0..3
    const float* con = val + (size_t)row * PARAM;
    float x0 = __ldg(&con[e0 & 15]);
    float x1 = __ldg(&con[(e0 + 1) & 15]);
    #pragma unroll
    for (int i = 0; i < 3; i++) {
        if (i < g) {
            x0 = fminf(fmaxf(x0 * scale, -1.0f), 1.0f);
            x1 = fminf(fmaxf(x1 * scale, -1.0f), 1.0f);
        }
    }
    float2* op = reinterpret_cast<float2*>(out + (size_t)row * PARAM);
    op[lane] = make_float2(x0, x1);
}

extern "C" void kernel_launch(void* const* d_in, const int* in_sizes, int n_in,
                              void* d_out, int out_size)
{
    const float* mat = (const float*)d_in[0];   // (32,1024,1024) f32
    const float* val = (const float*)d_in[1];   // (32,1024,64)  f32
    float* out = (float*)d_out;                 // (32,1024,64)  f32

    int rows = in_sizes[0] / GS;                // 32768
    rowsum_kernel<<<ABLKS, 256>>>(mat, rows);
    epilogue_kernel<<<(rows + 7) / 8, 256>>>(val, out, rows);
}

// round 5
// speedup vs baseline: 1.0910x; 1.0910x over previous
#include <cuda_runtime.h>

// gltrivmlp: out[b,g,0:16]=con, out[...,16:32]=clip(con*s),
// out[...,32:48]=clip^2, out[...,48:64]=clip^3, s=rowsum(mat[b,g,:])/16.
// (10-iter reference loop is a 16-lane shift register; fixed point after 3
// iterations; initial val[16:64] is dead.)
//
// R5: fused persistent (R3 base, R4 split reverted) + contiguous-block row
// mapping: each CTA streams 8 contiguous rows (32KB) per iteration instead of
// 8 rows scattered by 1184. Cuts concurrent DRAM streams 9472 -> 1184 to
// raise HBM page-hit rate.

#define GS    1024
#define PARAM 64
#define NSM   148
#define BLKS  (NSM * 8)

__global__ __launch_bounds__(256, 8)
void gltrivmlp_kernel(const float* __restrict__ mat,
                      const float* __restrict__ val,
                      float* __restrict__ out,
                      int rows)
{
    const int lane = threadIdx.x & 31;
    const int wib  = threadIdx.x >> 5;      // warp in block: 0..7

    // output mapping: lane -> elements {2*lane, 2*lane+1}; both in group g
    const int e0 = lane << 1;
    const int g  = e0 >> 4;                  // clip applications: 0..3

    // block b owns rows [b*8, b*8+8) each iteration, stride BLKS*8
    for (int base = blockIdx.x * 8; base < rows; base += BLKS * 8) {
        const int row = base + wib;
        if (row >= rows) break;

        const float4* m = reinterpret_cast<const float4*>(mat + (size_t)row * GS);
        float4 v0 = __ldcs(&m[lane +   0]);
        float4 v1 = __ldcs(&m[lane +  32]);
        float4 v2 = __ldcs(&m[lane +  64]);
        float4 v3 = __ldcs(&m[lane +  96]);
        float4 v4 = __ldcs(&m[lane + 128]);
        float4 v5 = __ldcs(&m[lane + 160]);
        float4 v6 = __ldcs(&m[lane + 192]);
        float4 v7 = __ldcs(&m[lane + 224]);
        float a0 = ((v0.x + v0.y) + (v0.z + v0.w)) + ((v1.x + v1.y) + (v1.z + v1.w));
        float a1 = ((v2.x + v2.y) + (v2.z + v2.w)) + ((v3.x + v3.y) + (v3.z + v3.w));
        float a2 = ((v4.x + v4.y) + (v4.z + v4.w)) + ((v5.x + v5.y) + (v5.z + v5.w));
        float a3 = ((v6.x + v6.y) + (v6.z + v6.w)) + ((v7.x + v7.y) + (v7.z + v7.w));

        float s = (a0 + a1) + (a2 + a3);
        #pragma unroll
        for (int o = 16; o > 0; o >>= 1)
            s += __shfl_xor_sync(0xFFFFFFFFu, s, o);
        const float scale = s * (1.0f / 16.0f);

        const float* con = val + (size_t)row * PARAM;
        float x0 = __ldg(&con[e0 & 15]);
        float x1 = __ldg(&con[(e0 + 1) & 15]);
        #pragma unroll
        for (int i = 0; i < 3; i++) {
            if (i < g) {
                x0 = fminf(fmaxf(x0 * scale, -1.0f), 1.0f);
                x1 = fminf(fmaxf(x1 * scale, -1.0f), 1.0f);
            }
        }
        float2* op = reinterpret_cast<float2*>(out + (size_t)row * PARAM);
        op[lane] = make_float2(x0, x1);
    }
}

extern "C" void kernel_launch(void* const* d_in, const int* in_sizes, int n_in,
                              void* d_out, int out_size)
{
    const float* mat = (const float*)d_in[0];   // (32,1024,1024) f32
    const float* val = (const float*)d_in[1];   // (32,1024,64)  f32
    float* out = (float*)d_out;                 // (32,1024,64)  f32

    int rows = in_sizes[0] / GS;                // 32768
    gltrivmlp_kernel<<<BLKS, 256>>>(mat, val, out, rows);
}